// round 2
// baseline (speedup 1.0000x reference)
#include <cuda_runtime.h>
#include <cuda_bf16.h>

// AdaptiveTokenMixer: out[b,n,:] = sum_k alpha[b,n,k] * x[b,n+k,:]
// alpha from masked temporal-decay softmax blended with softmax(w), sigmoid(beta).
// Shapes fixed by problem: B=8, N=4096, d=256, K=8.

constexpr int K_OFF = 8;     // kernel window
constexpr int D4    = 64;    // d / 4 (float4 columns)
constexpr int RG    = 32;    // rows per thread-group (rolling window length)
constexpr int G     = 2;     // row-groups per block
constexpr int NR    = RG * G;          // 64 rows per block
constexpr int NTHR  = D4 * G;          // 128 threads

// valid_mask dtype is unknown at compile time (JAX bool -> harness may pass
// uint8, int32, or float32). Probe bytes of elements known to be True
// (lengths >= N/2 guarantees mask[0..3] of batch 0 are all 1):
//   uint8:   byte[1] == 1
//   float32: byte[1] == 0, byte[3] == 0x3f   (1.0f = 00 00 80 3f)
//   int32:   byte[1] == 0, byte[3] == 0x00
__device__ __forceinline__ int probe_mask_mode(const unsigned char* vm) {
    if (vm[1] != 0) return 0;           // uint8
    if (vm[3] == 0x3f) return 2;        // float32
    return 1;                           // int32
}

__device__ __forceinline__ bool mask_at(const unsigned char* vm, int idx, int mode) {
    if (mode == 0) return vm[idx] != 0;
    if (mode == 1) return reinterpret_cast<const int*>(vm)[idx] != 0;
    return reinterpret_cast<const float*>(vm)[idx] != 0.0f;
}

__global__ __launch_bounds__(NTHR) void atm_kernel(
    const float* __restrict__ x,
    const float* __restrict__ dt,
    const unsigned char* __restrict__ vm,
    const float* __restrict__ w,
    const float* __restrict__ beta,
    float* __restrict__ out,
    int N)
{
    __shared__ float s_alpha[NR][K_OFF];

    const int b   = blockIdx.y;
    const int n0  = blockIdx.x * NR;
    const int tid = threadIdx.x;

    // -------- Phase 1: per-row alpha[8] into shared (one thread per row) ------
    if (tid < NR) {
        const int n = n0 + tid;
        const int mmode = probe_mask_mode(vm);
        const float*         dtb = dt + (size_t)b * N;
        const int            mb0 = b * N;   // element offset into mask

        // softmax(w) — 8 elems, L1-cached broadcast loads
        float wv[K_OFF];
        #pragma unroll
        for (int k = 0; k < K_OFF; k++) wv[k] = w[k];
        float wm = wv[0];
        #pragma unroll
        for (int k = 1; k < K_OFF; k++) wm = fmaxf(wm, wv[k]);
        float wsum = 0.f;
        #pragma unroll
        for (int k = 0; k < K_OFF; k++) { wv[k] = __expf(wv[k] - wm); wsum += wv[k]; }
        const float winv = 1.f / wsum;
        const float bsig = 1.f / (1.f + __expf(-beta[0]));

        const bool  v0  = mask_at(vm, mb0 + n, mmode);
        const float dtn = dtb[n];

        float sc[K_OFF];
        bool  cv[K_OFF];
        #pragma unroll
        for (int k = 0; k < K_OFF; k++) {
            const int  nk  = n + k;
            const bool inb = (nk < N);
            const int  nks = inb ? nk : n;              // OOB-safe index
            const bool c   = v0 && inb && mask_at(vm, mb0 + nks, mmode);
            const float td = (k == 0) ? 0.f : fmaxf(dtb[nks] - dtn, 0.f);
            cv[k] = c;
            sc[k] = c ? -td : -1e9f;
        }
        float m = sc[0];
        #pragma unroll
        for (int k = 1; k < K_OFF; k++) m = fmaxf(m, sc[k]);
        float th[K_OFF];
        float es = 0.f;
        #pragma unroll
        for (int k = 0; k < K_OFF; k++) { th[k] = __expf(sc[k] - m); es += th[k]; }
        const float einv = 1.f / es;

        float a[K_OFF];
        float asum = 0.f;
        #pragma unroll
        for (int k = 0; k < K_OFF; k++) {
            const float v = bsig * (wv[k] * winv) + (1.f - bsig) * (th[k] * einv);
            a[k] = cv[k] ? v : 0.f;
            asum += a[k];
        }
        const float ainv = 1.f / fmaxf(asum, 1e-8f);
        #pragma unroll
        for (int k = 0; k < K_OFF; k++) s_alpha[tid][k] = a[k] * ainv;
    }
    __syncthreads();

    // -------- Phase 2: rolling register window over rows, float4 columns ------
    const int c = tid & (D4 - 1);
    const int g = tid >> 6;                 // log2(D4) = 6
    const int rbase = n0 + g * RG;

    const float4* __restrict__ xcol =
        reinterpret_cast<const float4*>(x) + (size_t)b * N * D4 + c;
    float4* __restrict__ ocol =
        reinterpret_cast<float4*>(out) + (size_t)b * N * D4 + c;

    const float4 zero4 = make_float4(0.f, 0.f, 0.f, 0.f);
    float4 win[K_OFF];
    #pragma unroll
    for (int k = 0; k < K_OFF; k++) {
        const int n = rbase + k;
        win[k] = (n < N) ? xcol[(size_t)n * D4] : zero4;
    }

    #pragma unroll
    for (int r = 0; r < RG; r++) {
        const int n = rbase + r;
        const float* al = s_alpha[g * RG + r];
        float4 acc = zero4;
        #pragma unroll
        for (int k = 0; k < K_OFF; k++) {
            const float  a = al[k];
            const float4 v = win[(r + k) & (K_OFF - 1)];
            acc.x = fmaf(a, v.x, acc.x);
            acc.y = fmaf(a, v.y, acc.y);
            acc.z = fmaf(a, v.z, acc.z);
            acc.w = fmaf(a, v.w, acc.w);
        }
        ocol[(size_t)n * D4] = acc;

        if (r + 1 < RG) {
            const int nl = n + K_OFF;
            win[r & (K_OFF - 1)] = (nl < N) ? xcol[(size_t)nl * D4] : zero4;
        }
    }
}

extern "C" void kernel_launch(void* const* d_in, const int* in_sizes, int n_in,
                              void* d_out, int out_size)
{
    // metadata order: x [B,N,d] f32, delta_times [B,N] f32, valid_mask [B,N],
    //                 w [8] f32, beta [1] f32 ; output [B,N,d] f32
    const float*         x    = (const float*)d_in[0];
    const float*         dt   = (const float*)d_in[1];
    const unsigned char* vm   = (const unsigned char*)d_in[2];
    const float*         w    = (const float*)d_in[3];
    const float*         beta = (const float*)d_in[4];
    float*               out  = (float*)d_out;

    const int N = 4096;                       // fixed by problem
    const int BN = in_sizes[1];               // B*N
    const int B = BN / N;                     // 8

    dim3 grid((N + NR - 1) / NR, B);
    atm_kernel<<<grid, NTHR>>>(x, dt, vm, w, beta, out, N);
}

// round 3
// speedup vs baseline: 1.3208x; 1.3208x over previous
#include <cuda_runtime.h>
#include <cuda_bf16.h>

// AdaptiveTokenMixer: out[b,n,:] = sum_k alpha[b,n,k] * x[b,n+k,:]
// alpha from masked temporal-decay softmax blended with softmax(w), sigmoid(beta).
// Shapes fixed by problem: B=8, N=4096, d=256, K=8.

constexpr int K_OFF = 8;     // kernel window
constexpr int D4    = 64;    // d / 4 (float4 columns)
constexpr int RG    = 16;    // rows per thread-group (rolling window length)
constexpr int G     = 2;     // row-groups per block
constexpr int NR    = RG * G;          // 32 rows per block
constexpr int NTHR  = D4 * G;          // 128 threads

// valid_mask dtype probe (JAX bool may arrive as uint8 / int32 / float32).
// lengths >= N/2 guarantees mask[0..3] of batch 0 are all True:
//   uint8:   byte[1] == 1
//   float32: byte[1] == 0, byte[3] == 0x3f   (1.0f = 00 00 80 3f)
//   int32:   byte[1] == 0, byte[3] == 0x00
__device__ __forceinline__ int probe_mask_mode(const unsigned char* vm) {
    if (vm[1] != 0) return 0;           // uint8
    if (vm[3] == 0x3f) return 2;        // float32
    return 1;                           // int32
}

__device__ __forceinline__ bool mask_at(const unsigned char* vm, int idx, int mode) {
    if (mode == 0) return vm[idx] != 0;
    if (mode == 1) return reinterpret_cast<const int*>(vm)[idx] != 0;
    return reinterpret_cast<const float*>(vm)[idx] != 0.0f;
}

__global__ __launch_bounds__(NTHR) void atm_kernel(
    const float* __restrict__ x,
    const float* __restrict__ dt,
    const unsigned char* __restrict__ vm,
    const float* __restrict__ w,
    const float* __restrict__ beta,
    float* __restrict__ out,
    int N)
{
    __shared__ float s_alpha[NR][K_OFF];

    const int b   = blockIdx.y;
    const int n0  = blockIdx.x * NR;
    const int tid = threadIdx.x;

    // -------- Phase 1: per-row alpha[8] into shared (one thread per row) ------
    if (tid < NR) {
        const int n = n0 + tid;
        const int mmode = probe_mask_mode(vm);
        const float* dtb = dt + (size_t)b * N;
        const int    mb0 = b * N;   // element offset into mask

        // softmax(w) — 8 elems, L1-cached broadcast loads
        float wv[K_OFF];
        #pragma unroll
        for (int k = 0; k < K_OFF; k++) wv[k] = w[k];
        float wm = wv[0];
        #pragma unroll
        for (int k = 1; k < K_OFF; k++) wm = fmaxf(wm, wv[k]);
        float wsum = 0.f;
        #pragma unroll
        for (int k = 0; k < K_OFF; k++) { wv[k] = __expf(wv[k] - wm); wsum += wv[k]; }
        const float winv = 1.f / wsum;
        const float bsig = 1.f / (1.f + __expf(-beta[0]));

        const bool  v0  = mask_at(vm, mb0 + n, mmode);
        const float dtn = dtb[n];

        float sc[K_OFF];
        bool  cv[K_OFF];
        #pragma unroll
        for (int k = 0; k < K_OFF; k++) {
            const int  nk  = n + k;
            const bool inb = (nk < N);
            const int  nks = inb ? nk : n;              // OOB-safe index
            const bool c   = v0 && inb && mask_at(vm, mb0 + nks, mmode);
            const float td = (k == 0) ? 0.f : fmaxf(dtb[nks] - dtn, 0.f);
            cv[k] = c;
            sc[k] = c ? -td : -1e9f;
        }
        float m = sc[0];
        #pragma unroll
        for (int k = 1; k < K_OFF; k++) m = fmaxf(m, sc[k]);
        float th[K_OFF];
        float es = 0.f;
        #pragma unroll
        for (int k = 0; k < K_OFF; k++) { th[k] = __expf(sc[k] - m); es += th[k]; }
        const float einv = 1.f / es;

        float a[K_OFF];
        float asum = 0.f;
        #pragma unroll
        for (int k = 0; k < K_OFF; k++) {
            const float v = bsig * (wv[k] * winv) + (1.f - bsig) * (th[k] * einv);
            a[k] = cv[k] ? v : 0.f;
            asum += a[k];
        }
        const float ainv = 1.f / fmaxf(asum, 1e-8f);
        #pragma unroll
        for (int k = 0; k < K_OFF; k++) s_alpha[tid][k] = a[k] * ainv;
    }
    __syncthreads();

    // -------- Phase 2: rolling register window over rows, float4 columns ------
    const int c = tid & (D4 - 1);
    const int g = tid >> 6;                 // log2(D4) = 6
    const int rbase = n0 + g * RG;

    const float4* __restrict__ xcol =
        reinterpret_cast<const float4*>(x) + (size_t)b * N * D4 + c;
    float4* __restrict__ ocol =
        reinterpret_cast<float4*>(out) + (size_t)b * N * D4 + c;

    const float4 zero4 = make_float4(0.f, 0.f, 0.f, 0.f);
    float4 win[K_OFF];
    #pragma unroll
    for (int k = 0; k < K_OFF; k++) {
        const int n = rbase + k;
        win[k] = (n < N) ? xcol[(size_t)n * D4] : zero4;
    }

    #pragma unroll
    for (int r = 0; r < RG; r++) {
        const int n = rbase + r;
        const float* al = s_alpha[g * RG + r];
        float4 acc = zero4;
        #pragma unroll
        for (int k = 0; k < K_OFF; k++) {
            const float  a = al[k];
            const float4 v = win[(r + k) & (K_OFF - 1)];
            acc.x = fmaf(a, v.x, acc.x);
            acc.y = fmaf(a, v.y, acc.y);
            acc.z = fmaf(a, v.z, acc.z);
            acc.w = fmaf(a, v.w, acc.w);
        }
        ocol[(size_t)n * D4] = acc;

        if (r + 1 < RG) {
            const int nl = n + K_OFF;
            win[r & (K_OFF - 1)] = (nl < N) ? xcol[(size_t)nl * D4] : zero4;
        }
    }
}

extern "C" void kernel_launch(void* const* d_in, const int* in_sizes, int n_in,
                              void* d_out, int out_size)
{
    // metadata order: x [B,N,d] f32, delta_times [B,N] f32, valid_mask [B,N],
    //                 w [8] f32, beta [1] f32 ; output [B,N,d] f32
    const float*         x    = (const float*)d_in[0];
    const float*         dt   = (const float*)d_in[1];
    const unsigned char* vm   = (const unsigned char*)d_in[2];
    const float*         w    = (const float*)d_in[3];
    const float*         beta = (const float*)d_in[4];
    float*               out  = (float*)d_out;

    const int N = 4096;                       // fixed by problem
    const int BN = in_sizes[1];               // B*N
    const int B = BN / N;                     // 8

    dim3 grid((N + NR - 1) / NR, B);
    atm_kernel<<<grid, NTHR>>>(x, dt, vm, w, beta, out, N);
}